// round 11
// baseline (speedup 1.0000x reference)
#include <cuda_runtime.h>
#include <math.h>

#define PS 16
#define NB 32
#define IMGSZ (1024*1024)
#define TROWF 20                 // padded floats per tile row (mult of 4)
#define TB (PS*TROWF)            // 320 floats per batch slice

__device__ __forceinline__ float clamp01(float x) {
    return fminf(fmaxf(x, 0.0f), 1.0f);
}

// ---------------------------------------------------------------------------
// One CTA = one patch, all 32 batches, float4 everywhere.
// Thread t: bg = t>>6 (batch group of 8), q = t&63 (pixel quad: row=q>>2,
// qc=q&3). v4[8] registers hold the quad for 8 batches (32 regs).
//  stats: per-batch shfl-32 reduction of (sum, sumsq) over the 64 quad
//         owners (2 warps) -> smem partials -> threads 0..31 finalize.
//  code : thread 0 -> affine (alpha,beta,delta) or blur flag (CTA-uniform).
//  apply: float4 streaming stores from registers; blur path (rare) stages
//         the quad into a smem tile first (CTA-uniform branch, safe bar).
// ---------------------------------------------------------------------------
__global__ void __launch_bounds__(256, 4)
fused_kernel(const float* __restrict__ img,
             const float* __restrict__ noise,
             const float* __restrict__ r_strong,
             const float* __restrict__ r_drop,
             const float* __restrict__ r_else,
             const float* __restrict__ bright_f,
             const float* __restrict__ contrast_f,
             const float* __restrict__ slight_f,
             const int*   __restrict__ aug_choice,
             const int*   __restrict__ slight_choice,
             float* __restrict__ out) {
    __shared__ float part[8][8][2];          // [warp][k][sum,sumsq]
    __shared__ float s_q[NB], s_m[NB];
    __shared__ int   s_code;
    __shared__ float s_al, s_be, s_de;
    __shared__ float tile[NB * TB];          // 40 KB, used only for blur

    const int p  = blockIdx.x;               // patch 0..4095
    const int sy = p >> 6;
    const int px = p & 63;
    const int t  = threadIdx.x;
    const int bg = t >> 6;                   // batch group 0..3
    const int q  = t & 63;                   // quad id
    const int row = q >> 2;                  // 0..15
    const int qc  = q & 3;                   // quad col 0..3
    const int warp = t >> 5;

    const size_t gpix = (size_t)(sy * PS + row) * 1024 + px * PS + qc * 4;

    // ---- Phase 1: 8 front-batched float4 loads (batches bg*8 .. bg*8+7) ----
    float4 v[8];
#pragma unroll
    for (int k = 0; k < 8; ++k)
        v[k] = *reinterpret_cast<const float4*>(
                   img + gpix + (size_t)(bg * 8 + k) * IMGSZ);

    // ---- Phase 2: stats from registers (shfl over the 2-warp quad set) ----
#pragma unroll
    for (int k = 0; k < 8; ++k) {
        float s  = (v[k].x + v[k].y) + (v[k].z + v[k].w);
        float ss = fmaf(v[k].x, v[k].x,
                   fmaf(v[k].y, v[k].y,
                   fmaf(v[k].z, v[k].z, v[k].w * v[k].w)));
#pragma unroll
        for (int off = 16; off >= 1; off >>= 1) {
            s  += __shfl_down_sync(0xffffffffu, s,  off);
            ss += __shfl_down_sync(0xffffffffu, ss, off);
        }
        if ((t & 31) == 0) {
            part[warp][k][0] = s;
            part[warp][k][1] = ss;
        }
    }
    __syncthreads();

    if (t < NB) {                            // b = t
        const int bgg = t >> 3, k = t & 7;
        float s  = part[2 * bgg][k][0] + part[2 * bgg + 1][k][0];
        float ss = part[2 * bgg][k][1] + part[2 * bgg + 1][k][1];
        float mean = s * (1.0f / 256.0f);
        float var  = (ss - s * s * (1.0f / 256.0f)) * (1.0f / 255.0f); // ddof=1
        var = fmaxf(var, 0.0f);
        float std_ = sqrtf(var);
        float iq   = 1.0f - 2.0f * fabsf(mean - 0.5f);
        s_q[t] = (std_ + iq + var) * (1.0f / 3.0f);
        s_m[t] = mean;
    }
    __syncthreads();

    // ---- Phase 3: code (thread 0, CTA-uniform result) ----
    if (t == 0) {
        float qq = 0.f, m = 0.f;
#pragma unroll
        for (int b = 0; b < NB; ++b) { qq += s_q[b]; m += s_m[b]; }
        qq *= (1.0f / NB);
        m  *= (1.0f / NB);

        bool low    = qq < 0.7f;
        bool strong = low  && (r_strong[p] < 0.8f);
        bool drop   = low  && (qq < 0.3f) && (r_drop[p] < 0.1f);
        bool els    = !low && (r_else[p] < 0.3f);

        int code = 0;
        if (strong) code = aug_choice[p] + 1;      // 1..4
        if (els)    code = slight_choice[p] + 5;   // 5..6
        if (drop)   code = 7;

        float alpha = 1.f, beta = 0.f, delta = 0.f;
        if      (code == 1) beta = 0.1f;
        else if (code == 3) alpha = bright_f[p];
        else if (code == 4) { float cf = contrast_f[p]; alpha = cf; delta = m * (1.0f - cf); }
        else if (code == 5) beta = 0.05f;
        else if (code == 6) alpha = slight_f[p];
        else if (code == 7) alpha = 0.f;

        s_code = code; s_al = alpha; s_be = beta; s_de = delta;
    }
    __syncthreads();

    const int   code = s_code;               // uniform across CTA
    const float al   = s_al;
    const float be   = s_be;
    const float de   = s_de;

    // ---- Phase 4: apply + float4 streaming stores ----
    if (code == 2) {
        // rare path: stage quads to smem, then 3x3 zero-padded blur
#pragma unroll
        for (int k = 0; k < 8; ++k)
            *reinterpret_cast<float4*>(
                tile + (bg * 8 + k) * TB + row * TROWF + qc * 4) = v[k];
        __syncthreads();                     // CTA-uniform branch: safe
#pragma unroll 2
        for (int k = 0; k < 8; ++k) {
            const float* tb = tile + (bg * 8 + k) * TB;
            float rs[4];
#pragma unroll
            for (int j = 0; j < 4; ++j) {
                const int c = qc * 4 + j;
                float sum = 0.f;
#pragma unroll
                for (int dy = -1; dy <= 1; ++dy) {
                    const int rr = row + dy;
                    if (rr < 0 || rr >= PS) continue;
#pragma unroll
                    for (int dx = -1; dx <= 1; ++dx) {
                        const int cc = c + dx;
                        if (cc < 0 || cc >= PS) continue;
                        sum += tb[rr * TROWF + cc];
                    }
                }
                rs[j] = sum * (1.0f / 9.0f);
            }
            __stcs(reinterpret_cast<float4*>(
                       out + gpix + (size_t)(bg * 8 + k) * IMGSZ),
                   make_float4(rs[0], rs[1], rs[2], rs[3]));
        }
    } else if (be != 0.0f) {
        float4 n[8];
#pragma unroll
        for (int k = 0; k < 8; ++k)
            n[k] = *reinterpret_cast<const float4*>(
                       noise + gpix + (size_t)(bg * 8 + k) * IMGSZ);
#pragma unroll
        for (int k = 0; k < 8; ++k) {
            float4 r;
            r.x = clamp01(fmaf(be, n[k].x, fmaf(al, v[k].x, de)));
            r.y = clamp01(fmaf(be, n[k].y, fmaf(al, v[k].y, de)));
            r.z = clamp01(fmaf(be, n[k].z, fmaf(al, v[k].z, de)));
            r.w = clamp01(fmaf(be, n[k].w, fmaf(al, v[k].w, de)));
            __stcs(reinterpret_cast<float4*>(
                       out + gpix + (size_t)(bg * 8 + k) * IMGSZ), r);
        }
    } else {
#pragma unroll
        for (int k = 0; k < 8; ++k) {
            float4 r;
            r.x = clamp01(fmaf(al, v[k].x, de));
            r.y = clamp01(fmaf(al, v[k].y, de));
            r.z = clamp01(fmaf(al, v[k].z, de));
            r.w = clamp01(fmaf(al, v[k].w, de));
            __stcs(reinterpret_cast<float4*>(
                       out + gpix + (size_t)(bg * 8 + k) * IMGSZ), r);
        }
    }
}

extern "C" void kernel_launch(void* const* d_in, const int* in_sizes, int n_in,
                              void* d_out, int out_size) {
    const float* img           = (const float*)d_in[0];
    const float* noise         = (const float*)d_in[1];
    const float* r_strong      = (const float*)d_in[2];
    const float* r_drop        = (const float*)d_in[3];
    const float* r_else        = (const float*)d_in[4];
    const float* bright_f      = (const float*)d_in[5];
    const float* contrast_f    = (const float*)d_in[6];
    const float* slight_f      = (const float*)d_in[7];
    const int*   aug_choice    = (const int*)d_in[8];
    const int*   slight_choice = (const int*)d_in[9];
    float* out = (float*)d_out;

    fused_kernel<<<4096, 256>>>(img, noise, r_strong, r_drop, r_else,
                                bright_f, contrast_f, slight_f,
                                aug_choice, slight_choice, out);
}